// round 10
// baseline (speedup 1.0000x reference)
#include <cuda_runtime.h>
#include <cuda_fp16.h>
#include <cmath>
#include <cstdint>

#define L_SEQ  32768
#define DM     256
#define DH     256
#define NW1    512
#define CHUNK  32
#define NCHUNK (L_SEQ / CHUNK)   // 1024
#define NPOW   10                // KS stages: 2^10 = 1024

// ---------------- scratch ----------------
// Channel-interleaved layout: col 2h = re_h, col 2h+1 = im_h.
__device__ __half  g_BuH[(size_t)L_SEQ * NW1];    // GEMM1 out (fp16), scan input
__device__ __half  g_xf[(size_t)L_SEQ * DM];      // x in fp16
__device__ __half  g_hf[(size_t)L_SEQ * NW1];     // h in fp16 (scan output)
__device__ __half  g_W1f[NW1 * DM];               // [512][256]
__device__ __half  g_W2f[DM * NW1];               // [256][512]
__device__ float2  g_lam[DH];
__device__ float2  g_lamPow[NPOW * DH];           // (lambda^CHUNK)^(2^s)
__device__ float   g_carryf[(size_t)NCHUNK * NW1];
__device__ float   g_hinitf[(size_t)NCHUNK * NW1];

// ---------------- PTX helpers ----------------
__device__ __forceinline__ uint32_t smem_u32(const void* p) {
    uint32_t a;
    asm("{ .reg .u64 t; cvta.to.shared.u64 t, %1; cvt.u32.u64 %0, t; }" : "=r"(a) : "l"(p));
    return a;
}
__device__ __forceinline__ void cp16(uint32_t s, const void* g) {
    asm volatile("cp.async.cg.shared.global [%0], [%1], 16;" :: "r"(s), "l"(g));
}
__device__ __forceinline__ void cp_commit() {
    asm volatile("cp.async.commit_group;" ::: "memory");
}
__device__ __forceinline__ void ldsm4(uint32_t addr, uint32_t* r) {
    asm volatile("ldmatrix.sync.aligned.m8n8.x4.shared.b16 {%0,%1,%2,%3}, [%4];"
                 : "=r"(r[0]), "=r"(r[1]), "=r"(r[2]), "=r"(r[3]) : "r"(addr));
}
__device__ __forceinline__ void mma_f16(float* c, const uint32_t* a, const uint32_t* b) {
    asm volatile("mma.sync.aligned.m16n8k16.row.col.f32.f16.f16.f32 "
                 "{%0,%1,%2,%3},{%4,%5,%6,%7},{%8,%9},{%0,%1,%2,%3};"
                 : "+f"(c[0]), "+f"(c[1]), "+f"(c[2]), "+f"(c[3])
                 : "r"(a[0]), "r"(a[1]), "r"(a[2]), "r"(a[3]), "r"(b[0]), "r"(b[1]));
}

// ---------------- setup (params + weights merged) ----------------
__global__ void setup_all(const float* __restrict__ nu_log,
                          const float* __restrict__ theta_log,
                          const float* __restrict__ gamma_log,
                          const float* __restrict__ B_re,
                          const float* __restrict__ B_im,
                          const float* __restrict__ C_re,
                          const float* __restrict__ C_im) {
    int n = blockIdx.x;   // 0..511 : channel-interleaved (2h=re, 2h+1=im)
    int t = threadIdx.x;  // 0..255
    int h = n >> 1;
    int im = n & 1;
    float g = expf(gamma_log[h]);
    float w = (im ? B_im[h * DM + t] : B_re[h * DM + t]) * g;
    g_W1f[n * DM + t] = __float2half(w);
    float c2 = im ? -C_im[t * DH + h] : C_re[t * DH + h];
    g_W2f[t * NW1 + n] = __float2half(c2);
    if (n == 0) {   // block 0: lambda params (t = channel)
        double nu = exp((double)nu_log[t]);
        double th = exp((double)theta_log[t]);
        double r  = exp(-nu);
        g_lam[t]  = make_float2((float)(r * cos(th)), (float)(r * sin(th)));
        #pragma unroll
        for (int s = 0; s < NPOW; s++) {
            double sc = (double)CHUNK * (double)(1 << s);
            double rr = exp(-sc * nu);
            double aa = sc * th;
            g_lamPow[s * DH + t] = make_float2((float)(rr * cos(aa)), (float)(rr * sin(aa)));
        }
    }
}

__global__ void cvt_x(const float* __restrict__ x) {
    size_t i = (size_t)blockIdx.x * 256 + threadIdx.x;   // float4 index
    float4 v = ((const float4*)x)[i];
    __half2 p0 = __floats2half2_rn(v.x, v.y);
    __half2 p1 = __floats2half2_rn(v.z, v.w);
    uint2 u;
    u.x = *reinterpret_cast<uint32_t*>(&p0);
    u.y = *reinterpret_cast<uint32_t*>(&p1);
    *reinterpret_cast<uint2*>(g_xf + i * 4) = u;
}

// ---------------- fp16 mma.sync GEMM (single term, 4-stage pipeline) ---------
#define KC      32
#define PITCH   80
#define TILE_B  (128 * PITCH)              // 10240
#define NSTAGE  4
#define STAGE_B (2 * TILE_B)               // A + B tile
#define SMEM_G  (NSTAGE * STAGE_B)         // 81920 per CTA (x2 CTA/SM)
#define O_A 0
#define O_B TILE_B
// stash pitches: fp16 row 256B+16 (row shift 4 banks), fp32 row 512B+32 (shift 8)
#define SP_H 272
#define SP_F 544

template<int KTOT, int NGLOB, bool EPI, bool FUSE_SCAN, bool HALF_OUT>
__device__ __forceinline__ void mm_gemm_body(
    const __half* __restrict__ A, const __half* __restrict__ B,
    void* __restrict__ Cm, const float* __restrict__ X, const float* __restrict__ Dv)
{
    extern __shared__ char smem[];
    const uint32_t sb = smem_u32(smem);
    const int tid = threadIdx.x, wid = tid >> 5, l = tid & 31;
    const int rowbase = blockIdx.y * 128;
    const int colbase = blockIdx.x * 128;
    const int wm = wid & 3, wn = wid >> 2;

    float acc[2][8][4];
    #pragma unroll
    for (int i = 0; i < 2; i++)
        #pragma unroll
        for (int j = 0; j < 8; j++)
            #pragma unroll
            for (int q = 0; q < 4; q++) acc[i][j][q] = 0.f;

    const int srow = tid >> 1;
    const int sq   = (tid & 1) * 2;

    auto load_stage = [&](int c) {
        const uint32_t base = sb + (c & (NSTAGE - 1)) * STAGE_B;
        const int k0 = c * KC;
        const __half* gA = A + (size_t)(rowbase + srow) * KTOT + k0;
        const __half* gB = B + (size_t)(colbase + srow) * KTOT + k0;
        #pragma unroll
        for (int d = 0; d < 2; d++) {
            int q = sq + d;
            uint32_t so = srow * PITCH + q * 16;
            cp16(base + O_A + so, gA + q * 8);
            cp16(base + O_B + so, gB + q * 8);
        }
    };

    auto compute = [&](int c) {
        const uint32_t base = sb + (c & (NSTAGE - 1)) * STAGE_B;
        #pragma unroll
        for (int kk = 0; kk < 2; kk++) {
            const int k16 = kk * 16;
            uint32_t av[2][4], bv[4][4];
            const uint32_t arow_off =
                (uint32_t)(wm * 32 + (l & 15)) * PITCH + (uint32_t)(k16 + ((l >> 4) << 3)) * 2;
            const int g = l >> 3;
            const int nadd = ((g & 2) << 2) + (l & 7);
            const int kadd = k16 + ((g & 1) << 3);
            #pragma unroll
            for (int mt = 0; mt < 2; mt++)
                ldsm4(base + O_A + arow_off + (uint32_t)(mt * 16) * PITCH, av[mt]);
            #pragma unroll
            for (int p = 0; p < 4; p++)
                ldsm4(base + O_B + (uint32_t)(wn * 64 + p * 16 + nadd) * PITCH
                           + (uint32_t)kadd * 2, bv[p]);
            #pragma unroll
            for (int mt = 0; mt < 2; mt++)
                #pragma unroll
                for (int nt = 0; nt < 8; nt++)
                    mma_f16(acc[mt][nt], av[mt], &bv[nt >> 1][(nt & 1) * 2]);
        }
    };

    const int NCH = KTOT / KC;
    #pragma unroll
    for (int s = 0; s < NSTAGE - 1; s++) { load_stage(s); cp_commit(); }
    for (int c = 0; c < NCH; c++) {
        if (c + NSTAGE - 1 < NCH) load_stage(c + NSTAGE - 1);
        cp_commit();
        asm volatile("cp.async.wait_group %0;" :: "n"(NSTAGE - 1) : "memory");
        __syncthreads();
        compute(c);
        __syncthreads();
    }
    // smem pipeline fully consumed past this point — reuse as output stash

    const int erow = (l >> 2);
    const int ecol = (l & 3) * 2;
    #pragma unroll
    for (int mt = 0; mt < 2; mt++) {
        #pragma unroll
        for (int nt = 0; nt < 8; nt++) {
            int rl = wm * 32 + mt * 16 + erow;        // CTA-local row
            int cl = wn * 64 + nt * 8 + ecol;         // CTA-local col (even)
            float2 v0 = make_float2(acc[mt][nt][0], acc[mt][nt][1]);
            float2 v1 = make_float2(acc[mt][nt][2], acc[mt][nt][3]);
            if (HALF_OUT) {
                __half2 q0 = __floats2half2_rn(v0.x, v0.y);
                __half2 q1 = __floats2half2_rn(v1.x, v1.y);
                *(uint32_t*)(smem + rl * SP_H + cl * 2)       = *(uint32_t*)&q0;
                *(uint32_t*)(smem + (rl + 8) * SP_H + cl * 2) = *(uint32_t*)&q1;
            } else {
                *(float2*)(smem + rl * SP_F + cl * 4)       = v0;
                *(float2*)(smem + (rl + 8) * SP_F + cl * 4) = v1;
            }
        }
    }
    __syncthreads();

    // coalesced writeback from stash
    if (HALF_OUT) {
        int row = tid >> 1, hf = tid & 1;             // 2 threads/row, 128B each
        const char* sp = smem + row * SP_H + hf * 128;
        __half* C = (__half*)Cm + (size_t)(rowbase + row) * NGLOB + colbase + hf * 64;
        #pragma unroll
        for (int i = 0; i < 8; i++)
            *(uint4*)(C + i * 8) = *(const uint4*)(sp + i * 16);
    } else {
        #pragma unroll
        for (int rr = 0; rr < 2; rr++) {
            int row = (tid >> 2) + rr * 64;           // 4 threads/row, 128B each
            int q = tid & 3;
            const char* sp = smem + row * SP_F + q * 128;
            int c0 = colbase + q * 32;
            float* C = (float*)Cm + (size_t)(rowbase + row) * NGLOB + c0;
            if (EPI) {
                const float* Xp = X + (size_t)(rowbase + row) * DM + c0;
                #pragma unroll
                for (int i = 0; i < 8; i++) {
                    float4 v  = *(const float4*)(sp + i * 16);
                    float4 xv = *(const float4*)(Xp + i * 4);
                    float4 dv = *(const float4*)(Dv + c0 + i * 4);
                    v.x = fmaf(xv.x, dv.x, v.x); v.y = fmaf(xv.y, dv.y, v.y);
                    v.z = fmaf(xv.z, dv.z, v.z); v.w = fmaf(xv.w, dv.w, v.w);
                    *(float4*)(C + i * 4) = v;
                }
            } else {
                #pragma unroll
                for (int i = 0; i < 8; i++)
                    *(float4*)(C + i * 4) = *(const float4*)(sp + i * 16);
            }
        }
    }

    if (FUSE_SCAN) {
        // 4 sub-chunks of 32 rows x 64 complex channels -> 256 independent scans
        int ch = tid & 63;          // CTA-local complex channel (0..63)
        int ck = tid >> 6;          // sub-chunk (0..3): rows [32ck, 32ck+32)
        float2 lam = g_lam[(colbase >> 1) + ch];
        float hr = 0.f, hi = 0.f;
        const char* sp = smem + ck * 32 * SP_H + ch * 4;
        #pragma unroll 8
        for (int t = 0; t < CHUNK; t++) {
            uint32_t u = *(const uint32_t*)(sp + t * SP_H);
            __half2 hv = *(__half2*)&u;
            float br = __low2float(hv), bi = __high2float(hv);
            float nr = fmaf(lam.x, hr, fmaf(-lam.y, hi, br));
            float ni = fmaf(lam.x, hi, fmaf( lam.y, hr, bi));
            hr = nr; hi = ni;
        }
        int chunk = blockIdx.y * 4 + ck;
        *(float2*)&g_carryf[(size_t)chunk * NW1 + colbase + 2 * ch] =
            make_float2(hr, hi);
    }
}

// Wrappers: bind __device__ globals from DEVICE code only.
__global__ void __launch_bounds__(256, 2) gemm1_k() {
    mm_gemm_body<DM, NW1, false, true, true>(g_xf, g_W1f, g_BuH, nullptr, nullptr);
}
__global__ void __launch_bounds__(256, 2) gemm2_k(float* __restrict__ y,
                                                  const float* __restrict__ X,
                                                  const float* __restrict__ Dv) {
    mm_gemm_body<NW1, DM, true, false, false>(g_hf, g_W2f, y, X, Dv);
}

// ---------------- chunk prefix (Kogge-Stone over 1024 chunks) ----------------
__global__ void __launch_bounds__(NCHUNK) chunk_prefix_ks() {
    __shared__ float4 sm[NCHUNK];
    int c = threadIdx.x, j = blockIdx.x;   // j: channel pair 0..127
    float4 x = ((const float4*)g_carryf)[(size_t)c * 128 + j];
    sm[c] = x;
    __syncthreads();
    #pragma unroll
    for (int s = 0; s < NPOW; s++) {
        int d = 1 << s;
        float4 pv = make_float4(0.f, 0.f, 0.f, 0.f);
        if (c >= d) pv = sm[c - d];
        float2 p0 = g_lamPow[s * DH + 2 * j];
        float2 p1 = g_lamPow[s * DH + 2 * j + 1];
        __syncthreads();
        if (c >= d) {
            x.x += p0.x * pv.x - p0.y * pv.y;
            x.y += p0.x * pv.y + p0.y * pv.x;
            x.z += p1.x * pv.z - p1.y * pv.w;
            x.w += p1.x * pv.w + p1.y * pv.z;
        }
        sm[c] = x;
        __syncthreads();
    }
    float4 out = make_float4(0.f, 0.f, 0.f, 0.f);
    if (c > 0) out = sm[c - 1];
    ((float4*)g_hinitf)[(size_t)c * 128 + j] = out;
}

// ---------------- scan_apply: fp16 Bu -> fp16 h ------------------------------
__global__ void scan_apply() {
    int c = blockIdx.x, j = threadIdx.x;   // j: 0..127, 2 complex channels each
    float2 l0 = g_lam[2 * j], l1 = g_lam[2 * j + 1];
    float4 h = ((const float4*)g_hinitf)[(size_t)c * 128 + j];
    const uint2* base = (const uint2*)(g_BuH + (size_t)c * CHUNK * NW1) + j;
    __half* of = g_hf + (size_t)c * CHUNK * NW1 + 4 * j;
    #pragma unroll 8
    for (int t = 0; t < CHUNK; t++) {
        uint2 u = base[(size_t)t * 128];
        __half2 b0 = *(__half2*)&u.x;
        __half2 b1 = *(__half2*)&u.y;
        float nr0 = fmaf(l0.x, h.x, fmaf(-l0.y, h.y, __low2float(b0)));
        float ni0 = fmaf(l0.x, h.y, fmaf( l0.y, h.x, __high2float(b0)));
        float nr1 = fmaf(l1.x, h.z, fmaf(-l1.y, h.w, __low2float(b1)));
        float ni1 = fmaf(l1.x, h.w, fmaf( l1.y, h.z, __high2float(b1)));
        h = make_float4(nr0, ni0, nr1, ni1);
        __half2 p0 = __floats2half2_rn(nr0, ni0);
        __half2 p1 = __floats2half2_rn(nr1, ni1);
        uint2 o;
        o.x = *reinterpret_cast<uint32_t*>(&p0);
        o.y = *reinterpret_cast<uint32_t*>(&p1);
        *reinterpret_cast<uint2*>(of + (size_t)t * NW1) = o;
    }
}

// ---------------- entry ----------------
extern "C" void kernel_launch(void* const* d_in, const int* in_sizes, int n_in,
                              void* d_out, int out_size) {
    const float* x         = (const float*)d_in[0];
    const float* nu_log    = (const float*)d_in[1];
    const float* theta_log = (const float*)d_in[2];
    const float* gamma_log = (const float*)d_in[3];
    const float* B_re      = (const float*)d_in[4];
    const float* B_im      = (const float*)d_in[5];
    const float* C_re      = (const float*)d_in[6];
    const float* C_im      = (const float*)d_in[7];
    const float* Dv        = (const float*)d_in[8];
    float* y = (float*)d_out;

    cudaFuncSetAttribute(gemm1_k, cudaFuncAttributeMaxDynamicSharedMemorySize, SMEM_G);
    cudaFuncSetAttribute(gemm2_k, cudaFuncAttributeMaxDynamicSharedMemorySize, SMEM_G);

    setup_all<<<512, 256>>>(nu_log, theta_log, gamma_log, B_re, B_im, C_re, C_im);
    cvt_x<<<(L_SEQ * DM / 4) / 256, 256>>>(x);

    // GEMM1 (+ fused per-chunk carry scan): BuH = x @ W1T^T
    gemm1_k<<<dim3(NW1 / 128, L_SEQ / 128), 256, SMEM_G>>>();

    chunk_prefix_ks<<<128, NCHUNK>>>();
    scan_apply<<<NCHUNK, 128>>>();

    // GEMM2: y = h @ W2T^T + x*D
    gemm2_k<<<dim3(DM / 128, L_SEQ / 128), 256, SMEM_G>>>(y, x, Dv);
}